// round 2
// baseline (speedup 1.0000x reference)
#include <cuda_runtime.h>
#include <math.h>

// Problem constants
#define NN 50000
#define EE 400000
#define EP 450000      // E + N self loops
#define FF 128
#define H1 8
#define CC 64
#define HC 512         // H1*CC
#define BB 64
#define KK 10

// ---------------- scratch (device globals; no allocation allowed) ----------------
__device__ float g_h1[(size_t)NN * HC];      // x @ W1
__device__ float g_out1[(size_t)NN * HC];    // elu(gat1)
__device__ float g_h2[(size_t)NN * CC];      // out1 @ W2
__device__ float g_out2[(size_t)NN * CC];    // elu(gat2)
__device__ float g_as1[NN * H1];
__device__ float g_ad1[NN * H1];
__device__ float g_as2[NN];
__device__ float g_ad2[NN];
__device__ int   g_rowptr[NN + 1];
__device__ int   g_cursor[NN];
__device__ int   g_srcsorted[EP];
__device__ float g_pooled[BB * CC];

// ---------------- CSR build ----------------
__global__ void zero_counts_kernel() {
    int i = blockIdx.x * blockDim.x + threadIdx.x;
    if (i < NN) g_cursor[i] = 0;
}

__global__ void count_edges_kernel(const int* __restrict__ ei) {
    int i = blockIdx.x * blockDim.x + threadIdx.x;
    if (i >= EP) return;
    int d = (i < EE) ? ei[EE + i] : (i - EE);
    atomicAdd(&g_cursor[d], 1);
}

__global__ void scan_kernel() {
    __shared__ int part[1024];
    int t = threadIdx.x;
    const int CH = (NN + 1023) / 1024;  // 49
    int base = t * CH;
    int s = 0;
    for (int i = 0; i < CH; i++) {
        int idx = base + i;
        if (idx < NN) s += g_cursor[idx];
    }
    part[t] = s;
    __syncthreads();
    // inclusive Hillis-Steele scan
    for (int o = 1; o < 1024; o <<= 1) {
        int v = (t >= o) ? part[t - o] : 0;
        __syncthreads();
        part[t] += v;
        __syncthreads();
    }
    int run = part[t] - s;  // exclusive
    for (int i = 0; i < CH; i++) {
        int idx = base + i;
        if (idx < NN) {
            int c = g_cursor[idx];
            g_rowptr[idx] = run;
            g_cursor[idx] = run;   // reset cursor to segment start
            run += c;
        }
    }
    if (t == 1023) g_rowptr[NN] = part[1023];
}

__global__ void scatter_edges_kernel(const int* __restrict__ ei) {
    int i = blockIdx.x * blockDim.x + threadIdx.x;
    if (i >= EP) return;
    int s, d;
    if (i < EE) { s = ei[i]; d = ei[EE + i]; }
    else        { s = i - EE; d = s; }
    int pos = atomicAdd(&g_cursor[d], 1);
    g_srcsorted[pos] = s;
}

// ---------------- SGEMM (fp32 SIMT, tiled) ----------------
// C[M,Nd] = A[M,Kd] @ B[Kd,Nd], row-major. BM=128 BN=64 BK=16 TM=8 TN=4, 256 threads.
__global__ void sgemm_kernel(const float* __restrict__ A, const float* __restrict__ Bm,
                             float* __restrict__ Cm, int M, int Kd, int Nd) {
    const int BM = 128, BN = 64, BK = 16, TM = 8, TN = 4;
    __shared__ float As[BK][BM + 4];
    __shared__ float Bs[BK][BN];
    int tid = threadIdx.x;
    int tx = tid & 15;   // 0..15 -> BN/TN
    int ty = tid >> 4;   // 0..15 -> BM/TM
    int m0 = blockIdx.y * BM;
    int n0 = blockIdx.x * BN;

    float acc[TM][TN];
#pragma unroll
    for (int i = 0; i < TM; i++)
#pragma unroll
        for (int j = 0; j < TN; j++) acc[i][j] = 0.f;

    int ar = tid >> 2;          // 0..63
    int ac = (tid & 3) * 4;     // 0,4,8,12
    int bc = tid >> 4;          // 0..15
    int bj = (tid & 15) * 4;    // 0..60

    for (int k0 = 0; k0 < Kd; k0 += BK) {
#pragma unroll
        for (int rr = 0; rr < BM; rr += 64) {
            int r = ar + rr;
            int gm = m0 + r;
            float4 v = make_float4(0.f, 0.f, 0.f, 0.f);
            if (gm < M) v = *reinterpret_cast<const float4*>(A + (size_t)gm * Kd + k0 + ac);
            As[ac + 0][r] = v.x;
            As[ac + 1][r] = v.y;
            As[ac + 2][r] = v.z;
            As[ac + 3][r] = v.w;
        }
        {
            float4 v = *reinterpret_cast<const float4*>(Bm + (size_t)(k0 + bc) * Nd + n0 + bj);
            *reinterpret_cast<float4*>(&Bs[bc][bj]) = v;
        }
        __syncthreads();
#pragma unroll
        for (int kk = 0; kk < BK; kk++) {
            float a[TM], b[TN];
#pragma unroll
            for (int i = 0; i < TM; i++) a[i] = As[kk][ty * TM + i];
#pragma unroll
            for (int j = 0; j < TN; j++) b[j] = Bs[kk][tx * TN + j];
#pragma unroll
            for (int i = 0; i < TM; i++)
#pragma unroll
                for (int j = 0; j < TN; j++) acc[i][j] += a[i] * b[j];
        }
        __syncthreads();
    }
#pragma unroll
    for (int i = 0; i < TM; i++) {
        int gm = m0 + ty * TM + i;
        if (gm < M) {
            float4 v = make_float4(acc[i][0], acc[i][1], acc[i][2], acc[i][3]);
            *reinterpret_cast<float4*>(Cm + (size_t)gm * Nd + n0 + tx * TN) = v;
        }
    }
}

// ---------------- attention scores ----------------
// layer1: a_s[n,h] = dot(h1[n,h,:], att_src1[h,:]);   warp per node
__global__ void att1_kernel(const float* __restrict__ att_src, const float* __restrict__ att_dst) {
    __shared__ float s_as[HC], s_ad[HC];
    int t = threadIdx.x;
    s_as[t] = att_src[t];       s_as[t + 256] = att_src[t + 256];
    s_ad[t] = att_dst[t];       s_ad[t + 256] = att_dst[t + 256];
    __syncthreads();
    int w = t >> 5, lane = t & 31;
    int n = blockIdx.x * 8 + w;
    if (n >= NN) return;
    const float4* hp = reinterpret_cast<const float4*>(g_h1 + (size_t)n * HC) + lane * 4;
    float ds = 0.f, dd = 0.f;
#pragma unroll
    for (int q = 0; q < 4; q++) {
        float4 v = hp[q];
        int b = lane * 16 + q * 4;
        ds += v.x * s_as[b] + v.y * s_as[b + 1] + v.z * s_as[b + 2] + v.w * s_as[b + 3];
        dd += v.x * s_ad[b] + v.y * s_ad[b + 1] + v.z * s_ad[b + 2] + v.w * s_ad[b + 3];
    }
    ds += __shfl_xor_sync(~0u, ds, 1); ds += __shfl_xor_sync(~0u, ds, 2);
    dd += __shfl_xor_sync(~0u, dd, 1); dd += __shfl_xor_sync(~0u, dd, 2);
    if ((lane & 3) == 0) {
        int h = lane >> 2;
        g_as1[n * H1 + h] = ds;
        g_ad1[n * H1 + h] = dd;
    }
}

__global__ void att2_kernel(const float* __restrict__ att_src, const float* __restrict__ att_dst) {
    int t = threadIdx.x, w = t >> 5, lane = t & 31;
    int n = blockIdx.x * 8 + w;
    if (n >= NN) return;
    float v0 = g_h2[(size_t)n * CC + lane];
    float v1 = g_h2[(size_t)n * CC + lane + 32];
    float ds = v0 * __ldg(att_src + lane) + v1 * __ldg(att_src + lane + 32);
    float dd = v0 * __ldg(att_dst + lane) + v1 * __ldg(att_dst + lane + 32);
#pragma unroll
    for (int o = 16; o; o >>= 1) {
        ds += __shfl_xor_sync(~0u, ds, o);
        dd += __shfl_xor_sync(~0u, dd, o);
    }
    if (lane == 0) { g_as2[n] = ds; g_ad2[n] = dd; }
}

// ---------------- layer-1 aggregation (softmax + weighted sum + elu) ----------------
// block = node, warp = head. No atomics: CSR by dst.
__global__ void agg1_kernel(const float* __restrict__ bias) {
    __shared__ float ebuf[H1][64];
    int n = blockIdx.x;
    int h = threadIdx.x >> 5;
    int lane = threadIdx.x & 31;
    int base = g_rowptr[n];
    int deg = g_rowptr[n + 1] - base;
    float adn = g_ad1[n * H1 + h];

    float m = -INFINITY;
    for (int j = lane; j < deg; j += 32) {
        int s = g_srcsorted[base + j];
        float e = g_as1[s * H1 + h] + adn;
        e = e > 0.f ? e : 0.2f * e;
        m = fmaxf(m, e);
    }
#pragma unroll
    for (int o = 16; o; o >>= 1) m = fmaxf(m, __shfl_xor_sync(~0u, m, o));

    float sum = 0.f;
    for (int j = lane; j < deg; j += 32) {
        int s = g_srcsorted[base + j];
        float e = g_as1[s * H1 + h] + adn;
        e = e > 0.f ? e : 0.2f * e;
        float ex = __expf(e - m);
        if (j < 64) ebuf[h][j] = ex;
        sum += ex;
    }
#pragma unroll
    for (int o = 16; o; o >>= 1) sum += __shfl_xor_sync(~0u, sum, o);
    float inv = 1.f / (sum + 1e-16f);
    __syncwarp();

    float acc0 = 0.f, acc1 = 0.f;
    for (int j = 0; j < deg; j++) {
        int s = g_srcsorted[base + j];
        float ex;
        if (j < 64) ex = ebuf[h][j];
        else {
            float e = g_as1[s * H1 + h] + adn;
            e = e > 0.f ? e : 0.2f * e;
            ex = __expf(e - m);
        }
        float a = ex * inv;
        const float* hp = g_h1 + (size_t)s * HC + h * CC;
        acc0 += hp[lane] * a;
        acc1 += hp[lane + 32] * a;
    }
    float v0 = acc0 + bias[h * CC + lane];
    float v1 = acc1 + bias[h * CC + lane + 32];
    v0 = v0 > 0.f ? v0 : expm1f(v0);
    v1 = v1 > 0.f ? v1 : expm1f(v1);
    g_out1[(size_t)n * HC + h * CC + lane] = v0;
    g_out1[(size_t)n * HC + h * CC + lane + 32] = v1;
}

// ---------------- layer-2 aggregation (1 head, C=64) ----------------
__global__ void agg2_kernel(const float* __restrict__ bias) {
    __shared__ float ebuf[8][64];
    int w = threadIdx.x >> 5;
    int lane = threadIdx.x & 31;
    int n = blockIdx.x * 8 + w;
    if (n >= NN) return;
    int base = g_rowptr[n];
    int deg = g_rowptr[n + 1] - base;
    float adn = g_ad2[n];

    float m = -INFINITY;
    for (int j = lane; j < deg; j += 32) {
        int s = g_srcsorted[base + j];
        float e = g_as2[s] + adn;
        e = e > 0.f ? e : 0.2f * e;
        m = fmaxf(m, e);
    }
#pragma unroll
    for (int o = 16; o; o >>= 1) m = fmaxf(m, __shfl_xor_sync(~0u, m, o));

    float sum = 0.f;
    for (int j = lane; j < deg; j += 32) {
        int s = g_srcsorted[base + j];
        float e = g_as2[s] + adn;
        e = e > 0.f ? e : 0.2f * e;
        float ex = __expf(e - m);
        if (j < 64) ebuf[w][j] = ex;
        sum += ex;
    }
#pragma unroll
    for (int o = 16; o; o >>= 1) sum += __shfl_xor_sync(~0u, sum, o);
    float inv = 1.f / (sum + 1e-16f);
    __syncwarp();

    float acc0 = 0.f, acc1 = 0.f;
    for (int j = 0; j < deg; j++) {
        int s = g_srcsorted[base + j];
        float ex;
        if (j < 64) ex = ebuf[w][j];
        else {
            float e = g_as2[s] + adn;
            e = e > 0.f ? e : 0.2f * e;
            ex = __expf(e - m);
        }
        float a = ex * inv;
        const float* hp = g_h2 + (size_t)s * CC;
        acc0 += hp[lane] * a;
        acc1 += hp[lane + 32] * a;
    }
    float v0 = acc0 + bias[lane];
    float v1 = acc1 + bias[lane + 32];
    v0 = v0 > 0.f ? v0 : expm1f(v0);
    v1 = v1 > 0.f ? v1 : expm1f(v1);
    g_out2[(size_t)n * CC + lane] = v0;
    g_out2[(size_t)n * CC + lane + 32] = v1;
}

// ---------------- pooling (batch is sorted -> flush-on-change, few atomics) -----
__global__ void zero_pooled_kernel() {
    int i = blockIdx.x * blockDim.x + threadIdx.x;
    if (i < BB * CC) g_pooled[i] = 0.f;
}

__global__ void pool_kernel(const int* __restrict__ batch) {
    int c = threadIdx.x & 63;
    int nl = threadIdx.x >> 6;      // 0..3
    int n0 = blockIdx.x * 256;
    int nend = min(n0 + 256, NN);
    float acc = 0.f;
    int cur = -1;
    for (int n = n0 + nl; n < nend; n += 4) {
        int bt = batch[n];
        if (bt != cur) {
            if (cur >= 0) atomicAdd(&g_pooled[cur * CC + c], acc);
            cur = bt;
            acc = 0.f;
        }
        acc += g_out2[(size_t)n * CC + c];
    }
    if (cur >= 0) atomicAdd(&g_pooled[cur * CC + c], acc);
}

// ---------------- MLP head + log_softmax ----------------
__global__ void head_kernel(const float* __restrict__ lin1_w, const float* __restrict__ lin1_b,
                            const float* __restrict__ lin2_w, const float* __restrict__ lin2_b,
                            float* __restrict__ out) {
    __shared__ float p[CC], z[CC], lg[KK];
    __shared__ float lse;
    int t = threadIdx.x;
    int g = blockIdx.x;
    p[t] = g_pooled[g * CC + t];
    __syncthreads();
    float zz = lin1_b[t];
    for (int i = 0; i < CC; i++) zz += p[i] * lin1_w[i * CC + t];
    zz = zz > 0.f ? zz : expm1f(zz);
    z[t] = zz;
    __syncthreads();
    if (t < KK) {
        float l = lin2_b[t];
        for (int i = 0; i < CC; i++) l += z[i] * lin2_w[i * KK + t];
        lg[t] = l;
    }
    __syncthreads();
    if (t == 0) {
        float m = -INFINITY;
        for (int i = 0; i < KK; i++) m = fmaxf(m, lg[i]);
        float s = 0.f;
        for (int i = 0; i < KK; i++) s += expf(lg[i] - m);
        lse = m + logf(s);
    }
    __syncthreads();
    if (t < KK) out[g * KK + t] = lg[t] - lse;
}

// ---------------- launch ----------------
extern "C" void kernel_launch(void* const* d_in, const int* in_sizes, int n_in,
                              void* d_out, int out_size) {
    const float* x        = (const float*)d_in[0];
    const int*   ei       = (const int*)d_in[1];
    const int*   batch    = (const int*)d_in[2];
    const float* W1       = (const float*)d_in[3];
    const float* att_src1 = (const float*)d_in[4];
    const float* att_dst1 = (const float*)d_in[5];
    const float* b1       = (const float*)d_in[6];
    const float* W2       = (const float*)d_in[7];
    const float* att_src2 = (const float*)d_in[8];
    const float* att_dst2 = (const float*)d_in[9];
    const float* b2       = (const float*)d_in[10];
    const float* lin1_w   = (const float*)d_in[11];
    const float* lin1_b   = (const float*)d_in[12];
    const float* lin2_w   = (const float*)d_in[13];
    const float* lin2_b   = (const float*)d_in[14];
    float* out = (float*)d_out;

    // CSR build (recomputed every call; deterministic structure)
    zero_counts_kernel<<<(NN + 255) / 256, 256>>>();
    count_edges_kernel<<<(EP + 255) / 256, 256>>>(ei);
    scan_kernel<<<1, 1024>>>();
    scatter_edges_kernel<<<(EP + 255) / 256, 256>>>(ei);

    // layer 1
    {
        float* h1;
        cudaGetSymbolAddress((void**)&h1, g_h1);
        dim3 grid(HC / 64, (NN + 127) / 128);
        sgemm_kernel<<<grid, 256>>>(x, W1, h1, NN, FF, HC);
    }
    att1_kernel<<<(NN + 7) / 8, 256>>>(att_src1, att_dst1);
    agg1_kernel<<<NN, 256>>>(b1);

    // layer 2
    {
        float *o1, *h2;
        cudaGetSymbolAddress((void**)&o1, g_out1);
        cudaGetSymbolAddress((void**)&h2, g_h2);
        dim3 grid(CC / 64, (NN + 127) / 128);
        sgemm_kernel<<<grid, 256>>>(o1, W2, h2, NN, HC, CC);
    }
    att2_kernel<<<(NN + 7) / 8, 256>>>(att_src2, att_dst2);
    agg2_kernel<<<(NN + 7) / 8, 256>>>(b2);

    // pool + head
    zero_pooled_kernel<<<(BB * CC + 255) / 256, 256>>>();
    pool_kernel<<<(NN + 255) / 256, 256>>>(batch);
    head_kernel<<<BB, CC>>>(lin1_w, lin1_b, lin2_w, lin2_b, out);
}

// round 6
// speedup vs baseline: 1.1990x; 1.1990x over previous
#include <cuda_runtime.h>
#include <cuda_bf16.h>
#include <math.h>
#include <stdint.h>

// Problem constants
#define NN 50000
#define EE 400000
#define EP 450000      // E + N self loops
#define FF 128
#define H1 8
#define CC 64
#define HC 512         // H1*CC
#define BB 64
#define KK 10

// ---------------- scratch (device globals; no allocation allowed) ----------------
__device__ float g_h1[(size_t)NN * HC];      // x @ W1
__device__ float g_out1[(size_t)NN * HC];    // elu(gat1)
__device__ float g_h2[(size_t)NN * CC];      // out1 @ W2
__device__ float g_out2[(size_t)NN * CC];    // elu(gat2)
__device__ float g_as1[NN * H1];
__device__ float g_ad1[NN * H1];
__device__ float g_as2[NN];
__device__ float g_ad2[NN];
__device__ int   g_rowptr[NN + 1];
__device__ int   g_cursor[NN];
__device__ int   g_srcsorted[EP];
__device__ float g_pooled[BB * CC];
__device__ float g_W1T[HC * FF];             // W1^T : [512,128] (K-major B operand)
__device__ float g_W2T[CC * HC];             // W2^T : [64,512]

// ================= mma.sync helpers (sm_80+ PTX; valid on plain sm_103) =========
__device__ __forceinline__ void ldm_x4(uint32_t* r, uint32_t addr) {
    asm volatile("ldmatrix.sync.aligned.m8n8.x4.shared.b16 {%0,%1,%2,%3}, [%4];"
        : "=r"(r[0]), "=r"(r[1]), "=r"(r[2]), "=r"(r[3]) : "r"(addr));
}
__device__ __forceinline__ void ldm_x2(uint32_t* r, uint32_t addr) {
    asm volatile("ldmatrix.sync.aligned.m8n8.x2.shared.b16 {%0,%1}, [%2];"
        : "=r"(r[0]), "=r"(r[1]) : "r"(addr));
}
__device__ __forceinline__ void mma_bf16(float* c, const uint32_t* a, const uint32_t* b) {
    asm volatile("mma.sync.aligned.m16n8k16.row.col.f32.bf16.bf16.f32 "
        "{%0,%1,%2,%3}, {%4,%5,%6,%7}, {%8,%9}, {%0,%1,%2,%3};"
        : "+f"(c[0]), "+f"(c[1]), "+f"(c[2]), "+f"(c[3])
        : "r"(a[0]), "r"(a[1]), "r"(a[2]), "r"(a[3]), "r"(b[0]), "r"(b[1]));
}

// split a float into bf16 hi + bf16 lo (residual)
__device__ __forceinline__ void bsplit(float x, uint32_t& h, uint32_t& l) {
    __nv_bfloat16 hb = __float2bfloat16(x);
    float r = x - __bfloat162float(hb);
    h = (uint32_t)__bfloat16_as_ushort(hb);
    l = (uint32_t)__bfloat16_as_ushort(__float2bfloat16(r));
}
__device__ __forceinline__ void bsplit4(float4 v, uint2& hi, uint2& lo) {
    uint32_t h0, l0, h1, l1, h2, l2, h3, l3;
    bsplit(v.x, h0, l0); bsplit(v.y, h1, l1);
    bsplit(v.z, h2, l2); bsplit(v.w, h3, l3);
    hi.x = h0 | (h1 << 16); hi.y = h2 | (h3 << 16);
    lo.x = l0 | (l1 << 16); lo.y = l2 | (l3 << 16);
}

// ================= bf16x3 tensor-core GEMM (mma.sync) =================
// C[M,NTOT] = A[M,KTOT] @ BT[NTOT,KTOT]^T   (BT is K-major: BT[n][k])
// BM=128, BK=32 floats; 256 threads (8 warps, 2x4 warp grid; warp tile 64 x BN/4).
// 3 passes per tile: Ahi*Bhi + Alo*Bhi + Ahi*Blo (bf16x3 precision trick).
template <int KTOT, int BN>
__global__ void __launch_bounds__(256, 2) gemm_bf16x3_kernel(
    const float* __restrict__ A, const float* __restrict__ BT,
    float* __restrict__ C, int M, int NTOT) {
    constexpr int BM = 128, BK = 32;
    constexpr int LDB_BYTES = 80;     // 32 bf16 padded to 40 (80 bytes): conflict-free ldmatrix
    constexpr int WN = BN / 4;        // warp n-tile (32 or 16)
    constexpr int NT = WN / 8;        // n mma tiles per warp (4 or 2)
    constexpr int AV = 4;             // A float4 per thread (128*8/256)
    constexpr int BV = (BN * 8) / 256;

    __shared__ __align__(16) char sAhi[BM * LDB_BYTES];
    __shared__ __align__(16) char sAlo[BM * LDB_BYTES];
    __shared__ __align__(16) char sBhi[BN * LDB_BYTES];
    __shared__ __align__(16) char sBlo[BN * LDB_BYTES];

    const int tid = threadIdx.x, wid = tid >> 5, lane = tid & 31;
    const int wm = wid & 1, wn = wid >> 1;   // 2 x 4 warp grid
    const int m0 = blockIdx.y * BM, n0 = blockIdx.x * BN;

    const uint32_t aHiB = (uint32_t)__cvta_generic_to_shared(sAhi);
    const uint32_t aLoB = (uint32_t)__cvta_generic_to_shared(sAlo);
    const uint32_t bHiB = (uint32_t)__cvta_generic_to_shared(sBhi);
    const uint32_t bLoB = (uint32_t)__cvta_generic_to_shared(sBlo);

    float acc[4][NT][4];
#pragma unroll
    for (int i = 0; i < 4; i++)
#pragma unroll
        for (int j = 0; j < NT; j++)
#pragma unroll
            for (int q = 0; q < 4; q++) acc[i][j][q] = 0.f;

    // ldmatrix per-lane address offsets
    const int a_row = lane & 15;                  // row within 16-row tile
    const int a_col = (lane >> 4) << 3;           // 0 or 8 (k offset)
    const int b_row = lane & 7;
    const int b_col = ((lane >> 3) & 1) << 3;

    for (int k0 = 0; k0 < KTOT; k0 += BK) {
        // ---- global loads into registers ----
        float4 av[AV];
#pragma unroll
        for (int i = 0; i < AV; i++) {
            int f = tid + i * 256;                // float4 index
            int row = f >> 3, c4 = f & 7;
            int gm = m0 + row;
            av[i] = (gm < M)
                ? __ldg(reinterpret_cast<const float4*>(A + (size_t)gm * KTOT + k0 + c4 * 4))
                : make_float4(0.f, 0.f, 0.f, 0.f);
        }
        float4 bv[BV];
#pragma unroll
        for (int i = 0; i < BV; i++) {
            int f = tid + i * 256;
            int row = f >> 3, c4 = f & 7;
            bv[i] = __ldg(reinterpret_cast<const float4*>(BT + (size_t)(n0 + row) * KTOT + k0 + c4 * 4));
        }
        __syncthreads();   // previous compute done with smem
        // ---- split to bf16 hi/lo and store to smem ----
#pragma unroll
        for (int i = 0; i < AV; i++) {
            int f = tid + i * 256;
            int row = f >> 3, c4 = f & 7;
            uint2 hi, lo;
            bsplit4(av[i], hi, lo);
            int off = row * LDB_BYTES + c4 * 8;
            *reinterpret_cast<uint2*>(sAhi + off) = hi;
            *reinterpret_cast<uint2*>(sAlo + off) = lo;
        }
#pragma unroll
        for (int i = 0; i < BV; i++) {
            int f = tid + i * 256;
            int row = f >> 3, c4 = f & 7;
            uint2 hi, lo;
            bsplit4(bv[i], hi, lo);
            int off = row * LDB_BYTES + c4 * 8;
            *reinterpret_cast<uint2*>(sBhi + off) = hi;
            *reinterpret_cast<uint2*>(sBlo + off) = lo;
        }
        __syncthreads();
        // ---- compute: 2 k-steps of 16, 3 passes each ----
#pragma unroll
        for (int ks = 0; ks < 2; ks++) {
            int kk = ks * 16;
            uint32_t ah[4][4], al[4][4], bh[NT][2], bl[NT][2];
#pragma unroll
            for (int mt = 0; mt < 4; mt++) {
                uint32_t off = (uint32_t)((wm * 64 + mt * 16 + a_row) * LDB_BYTES + (kk + a_col) * 2);
                ldm_x4(ah[mt], aHiB + off);
                ldm_x4(al[mt], aLoB + off);
            }
#pragma unroll
            for (int nt = 0; nt < NT; nt++) {
                uint32_t off = (uint32_t)((wn * WN + nt * 8 + b_row) * LDB_BYTES + (kk + b_col) * 2);
                ldm_x2(bh[nt], bHiB + off);
                ldm_x2(bl[nt], bLoB + off);
            }
#pragma unroll
            for (int mt = 0; mt < 4; mt++)
#pragma unroll
                for (int nt = 0; nt < NT; nt++) mma_bf16(acc[mt][nt], ah[mt], bh[nt]);
#pragma unroll
            for (int mt = 0; mt < 4; mt++)
#pragma unroll
                for (int nt = 0; nt < NT; nt++) mma_bf16(acc[mt][nt], al[mt], bh[nt]);
#pragma unroll
            for (int mt = 0; mt < 4; mt++)
#pragma unroll
                for (int nt = 0; nt < NT; nt++) mma_bf16(acc[mt][nt], ah[mt], bl[nt]);
        }
    }

    // ---- epilogue: fp32 accum straight to global ----
#pragma unroll
    for (int mt = 0; mt < 4; mt++) {
        int r0 = m0 + wm * 64 + mt * 16 + (lane >> 2);
        int r1 = r0 + 8;
#pragma unroll
        for (int nt = 0; nt < NT; nt++) {
            int col = n0 + wn * WN + nt * 8 + (lane & 3) * 2;
            if (r0 < M)
                *reinterpret_cast<float2*>(C + (size_t)r0 * NTOT + col) =
                    make_float2(acc[mt][nt][0], acc[mt][nt][1]);
            if (r1 < M)
                *reinterpret_cast<float2*>(C + (size_t)r1 * NTOT + col) =
                    make_float2(acc[mt][nt][2], acc[mt][nt][3]);
        }
    }
}

// ---------------- weight transpose: dst[c*R + r] = src[r*C + c] ----------------
__global__ void transpose_kernel(const float* __restrict__ src, float* __restrict__ dst,
                                 int R, int C) {
    int i = blockIdx.x * blockDim.x + threadIdx.x;
    if (i < R * C) {
        int r = i / C, c = i % C;
        dst[c * R + r] = src[i];
    }
}

// ---------------- CSR build ----------------
__global__ void zero_counts_kernel() {
    int i = blockIdx.x * blockDim.x + threadIdx.x;
    if (i < NN) g_cursor[i] = 0;
}

__global__ void count_edges_kernel(const int* __restrict__ ei) {
    int i = blockIdx.x * blockDim.x + threadIdx.x;
    if (i >= EP) return;
    int d = (i < EE) ? ei[EE + i] : (i - EE);
    atomicAdd(&g_cursor[d], 1);
}

__global__ void scan_kernel() {
    __shared__ int part[1024];
    int t = threadIdx.x;
    const int CH = (NN + 1023) / 1024;  // 49
    int base = t * CH;
    int s = 0;
    for (int i = 0; i < CH; i++) {
        int idx = base + i;
        if (idx < NN) s += g_cursor[idx];
    }
    part[t] = s;
    __syncthreads();
    for (int o = 1; o < 1024; o <<= 1) {
        int v = (t >= o) ? part[t - o] : 0;
        __syncthreads();
        part[t] += v;
        __syncthreads();
    }
    int run = part[t] - s;  // exclusive
    for (int i = 0; i < CH; i++) {
        int idx = base + i;
        if (idx < NN) {
            int c = g_cursor[idx];
            g_rowptr[idx] = run;
            g_cursor[idx] = run;
            run += c;
        }
    }
    if (t == 1023) g_rowptr[NN] = part[1023];
}

__global__ void scatter_edges_kernel(const int* __restrict__ ei) {
    int i = blockIdx.x * blockDim.x + threadIdx.x;
    if (i >= EP) return;
    int s, d;
    if (i < EE) { s = ei[i]; d = ei[EE + i]; }
    else        { s = i - EE; d = s; }
    int pos = atomicAdd(&g_cursor[d], 1);
    g_srcsorted[pos] = s;
}

// ---------------- attention scores ----------------
__global__ void att1_kernel(const float* __restrict__ att_src, const float* __restrict__ att_dst) {
    __shared__ float s_as[HC], s_ad[HC];
    int t = threadIdx.x;
    s_as[t] = att_src[t];       s_as[t + 256] = att_src[t + 256];
    s_ad[t] = att_dst[t];       s_ad[t + 256] = att_dst[t + 256];
    __syncthreads();
    int w = t >> 5, lane = t & 31;
    int n = blockIdx.x * 8 + w;
    if (n >= NN) return;
    const float4* hp = reinterpret_cast<const float4*>(g_h1 + (size_t)n * HC) + lane * 4;
    float ds = 0.f, dd = 0.f;
#pragma unroll
    for (int q = 0; q < 4; q++) {
        float4 v = hp[q];
        int b = lane * 16 + q * 4;
        ds += v.x * s_as[b] + v.y * s_as[b + 1] + v.z * s_as[b + 2] + v.w * s_as[b + 3];
        dd += v.x * s_ad[b] + v.y * s_ad[b + 1] + v.z * s_ad[b + 2] + v.w * s_ad[b + 3];
    }
    ds += __shfl_xor_sync(~0u, ds, 1); ds += __shfl_xor_sync(~0u, ds, 2);
    dd += __shfl_xor_sync(~0u, dd, 1); dd += __shfl_xor_sync(~0u, dd, 2);
    if ((lane & 3) == 0) {
        int h = lane >> 2;
        g_as1[n * H1 + h] = ds;
        g_ad1[n * H1 + h] = dd;
    }
}

__global__ void att2_kernel(const float* __restrict__ att_src, const float* __restrict__ att_dst) {
    int t = threadIdx.x, w = t >> 5, lane = t & 31;
    int n = blockIdx.x * 8 + w;
    if (n >= NN) return;
    float v0 = g_h2[(size_t)n * CC + lane];
    float v1 = g_h2[(size_t)n * CC + lane + 32];
    float ds = v0 * __ldg(att_src + lane) + v1 * __ldg(att_src + lane + 32);
    float dd = v0 * __ldg(att_dst + lane) + v1 * __ldg(att_dst + lane + 32);
#pragma unroll
    for (int o = 16; o; o >>= 1) {
        ds += __shfl_xor_sync(~0u, ds, o);
        dd += __shfl_xor_sync(~0u, dd, o);
    }
    if (lane == 0) { g_as2[n] = ds; g_ad2[n] = dd; }
}

// ---------------- layer-1 aggregation (softmax + weighted sum + elu) ----------------
__global__ void agg1_kernel(const float* __restrict__ bias) {
    __shared__ float ebuf[H1][64];
    int n = blockIdx.x;
    int h = threadIdx.x >> 5;
    int lane = threadIdx.x & 31;
    int base = g_rowptr[n];
    int deg = g_rowptr[n + 1] - base;
    float adn = g_ad1[n * H1 + h];

    float m = -INFINITY;
    for (int j = lane; j < deg; j += 32) {
        int s = g_srcsorted[base + j];
        float e = g_as1[s * H1 + h] + adn;
        e = e > 0.f ? e : 0.2f * e;
        m = fmaxf(m, e);
    }
#pragma unroll
    for (int o = 16; o; o >>= 1) m = fmaxf(m, __shfl_xor_sync(~0u, m, o));

    float sum = 0.f;
    for (int j = lane; j < deg; j += 32) {
        int s = g_srcsorted[base + j];
        float e = g_as1[s * H1 + h] + adn;
        e = e > 0.f ? e : 0.2f * e;
        float ex = __expf(e - m);
        if (j < 64) ebuf[h][j] = ex;
        sum += ex;
    }
#pragma unroll
    for (int o = 16; o; o >>= 1) sum += __shfl_xor_sync(~0u, sum, o);
    float inv = 1.f / (sum + 1e-16f);
    __syncwarp();

    float acc0 = 0.f, acc1 = 0.f;
    for (int j = 0; j < deg; j++) {
        int s = g_srcsorted[base + j];
        float ex;
        if (j < 64) ex = ebuf[h][j];
        else {
            float e = g_as1[s * H1 + h] + adn;
            e = e > 0.f ? e : 0.2f * e;
            ex = __expf(e - m);
        }
        float a = ex * inv;
        const float* hp = g_h1 + (size_t)s * HC + h * CC;
        acc0 += hp[lane] * a;
        acc1 += hp[lane + 32] * a;
    }
    float v0 = acc0 + bias[h * CC + lane];
    float v1 = acc1 + bias[h * CC + lane + 32];
    v0 = v0 > 0.f ? v0 : expm1f(v0);
    v1 = v1 > 0.f ? v1 : expm1f(v1);
    g_out1[(size_t)n * HC + h * CC + lane] = v0;
    g_out1[(size_t)n * HC + h * CC + lane + 32] = v1;
}

// ---------------- layer-2 aggregation (1 head, C=64) ----------------
__global__ void agg2_kernel(const float* __restrict__ bias) {
    __shared__ float ebuf[8][64];
    int w = threadIdx.x >> 5;
    int lane = threadIdx.x & 31;
    int n = blockIdx.x * 8 + w;
    if (n >= NN) return;
    int base = g_rowptr[n];
    int deg = g_rowptr[n + 1] - base;
    float adn = g_ad2[n];

    float m = -INFINITY;
    for (int j = lane; j < deg; j += 32) {
        int s = g_srcsorted[base + j];
        float e = g_as2[s] + adn;
        e = e > 0.f ? e : 0.2f * e;
        m = fmaxf(m, e);
    }
#pragma unroll
    for (int o = 16; o; o >>= 1) m = fmaxf(m, __shfl_xor_sync(~0u, m, o));

    float sum = 0.f;
    for (int j = lane; j < deg; j += 32) {
        int s = g_srcsorted[base + j];
        float e = g_as2[s] + adn;
        e = e > 0.f ? e : 0.2f * e;
        float ex = __expf(e - m);
        if (j < 64) ebuf[w][j] = ex;
        sum += ex;
    }
#pragma unroll
    for (int o = 16; o; o >>= 1) sum += __shfl_xor_sync(~0u, sum, o);
    float inv = 1.f / (sum + 1e-16f);
    __syncwarp();

    float acc0 = 0.f, acc1 = 0.f;
    for (int j = 0; j < deg; j++) {
        int s = g_srcsorted[base + j];
        float ex;
        if (j < 64) ex = ebuf[w][j];
        else {
            float e = g_as2[s] + adn;
            e = e > 0.f ? e : 0.2f * e;
            ex = __expf(e - m);
        }
        float a = ex * inv;
        const float* hp = g_h2 + (size_t)s * CC;
        acc0 += hp[lane] * a;
        acc1 += hp[lane + 32] * a;
    }
    float v0 = acc0 + bias[lane];
    float v1 = acc1 + bias[lane + 32];
    v0 = v0 > 0.f ? v0 : expm1f(v0);
    v1 = v1 > 0.f ? v1 : expm1f(v1);
    g_out2[(size_t)n * CC + lane] = v0;
    g_out2[(size_t)n * CC + lane + 32] = v1;
}

// ---------------- pooling ----------------
__global__ void zero_pooled_kernel() {
    int i = blockIdx.x * blockDim.x + threadIdx.x;
    if (i < BB * CC) g_pooled[i] = 0.f;
}

__global__ void pool_kernel(const int* __restrict__ batch) {
    int c = threadIdx.x & 63;
    int nl = threadIdx.x >> 6;      // 0..3
    int n0 = blockIdx.x * 256;
    int nend = min(n0 + 256, NN);
    float acc = 0.f;
    int cur = -1;
    for (int n = n0 + nl; n < nend; n += 4) {
        int bt = batch[n];
        if (bt != cur) {
            if (cur >= 0) atomicAdd(&g_pooled[cur * CC + c], acc);
            cur = bt;
            acc = 0.f;
        }
        acc += g_out2[(size_t)n * CC + c];
    }
    if (cur >= 0) atomicAdd(&g_pooled[cur * CC + c], acc);
}

// ---------------- MLP head + log_softmax ----------------
__global__ void head_kernel(const float* __restrict__ lin1_w, const float* __restrict__ lin1_b,
                            const float* __restrict__ lin2_w, const float* __restrict__ lin2_b,
                            float* __restrict__ out) {
    __shared__ float p[CC], z[CC], lg[KK];
    __shared__ float lse;
    int t = threadIdx.x;
    int g = blockIdx.x;
    p[t] = g_pooled[g * CC + t];
    __syncthreads();
    float zz = lin1_b[t];
    for (int i = 0; i < CC; i++) zz += p[i] * lin1_w[i * CC + t];
    zz = zz > 0.f ? zz : expm1f(zz);
    z[t] = zz;
    __syncthreads();
    if (t < KK) {
        float l = lin2_b[t];
        for (int i = 0; i < CC; i++) l += z[i] * lin2_w[i * KK + t];
        lg[t] = l;
    }
    __syncthreads();
    if (t == 0) {
        float m = -INFINITY;
        for (int i = 0; i < KK; i++) m = fmaxf(m, lg[i]);
        float s = 0.f;
        for (int i = 0; i < KK; i++) s += expf(lg[i] - m);
        lse = m + logf(s);
    }
    __syncthreads();
    if (t < KK) out[g * KK + t] = lg[t] - lse;
}

// ---------------- launch ----------------
extern "C" void kernel_launch(void* const* d_in, const int* in_sizes, int n_in,
                              void* d_out, int out_size) {
    const float* x        = (const float*)d_in[0];
    const int*   ei       = (const int*)d_in[1];
    const int*   batch    = (const int*)d_in[2];
    const float* W1       = (const float*)d_in[3];
    const float* att_src1 = (const float*)d_in[4];
    const float* att_dst1 = (const float*)d_in[5];
    const float* b1       = (const float*)d_in[6];
    const float* W2       = (const float*)d_in[7];
    const float* att_src2 = (const float*)d_in[8];
    const float* att_dst2 = (const float*)d_in[9];
    const float* b2       = (const float*)d_in[10];
    const float* lin1_w   = (const float*)d_in[11];
    const float* lin1_b   = (const float*)d_in[12];
    const float* lin2_w   = (const float*)d_in[13];
    const float* lin2_b   = (const float*)d_in[14];
    float* out = (float*)d_out;

    float *w1t, *w2t, *h1, *o1, *h2;
    cudaGetSymbolAddress((void**)&w1t, g_W1T);
    cudaGetSymbolAddress((void**)&w2t, g_W2T);
    cudaGetSymbolAddress((void**)&h1, g_h1);
    cudaGetSymbolAddress((void**)&o1, g_out1);
    cudaGetSymbolAddress((void**)&h2, g_h2);

    // weight transposes (K-major B operands)
    transpose_kernel<<<(FF * HC + 255) / 256, 256>>>(W1, w1t, FF, HC);
    transpose_kernel<<<(HC * CC + 255) / 256, 256>>>(W2, w2t, HC, CC);

    // CSR build
    zero_counts_kernel<<<(NN + 255) / 256, 256>>>();
    count_edges_kernel<<<(EP + 255) / 256, 256>>>(ei);
    scan_kernel<<<1, 1024>>>();
    scatter_edges_kernel<<<(EP + 255) / 256, 256>>>(ei);

    // layer 1: h1 = x @ W1  (bf16x3 tensor cores)
    {
        dim3 grid(HC / 128, (NN + 127) / 128);
        gemm_bf16x3_kernel<FF, 128><<<grid, 256>>>(x, w1t, h1, NN, HC);
    }
    att1_kernel<<<(NN + 7) / 8, 256>>>(att_src1, att_dst1);
    agg1_kernel<<<NN, 256>>>(b1);

    // layer 2: h2 = out1 @ W2
    {
        dim3 grid(CC / 64, (NN + 127) / 128);
        gemm_bf16x3_kernel<HC, 64><<<grid, 256>>>(o1, w2t, h2, NN, CC);
    }
    att2_kernel<<<(NN + 7) / 8, 256>>>(att_src2, att_dst2);
    agg2_kernel<<<(NN + 7) / 8, 256>>>(b2);

    // pool + head
    zero_pooled_kernel<<<(BB * CC + 255) / 256, 256>>>();
    pool_kernel<<<(NN + 255) / 256, 256>>>(batch);
    head_kernel<<<BB, CC>>>(lin1_w, lin1_b, lin2_w, lin2_b, out);
}

// round 10
// speedup vs baseline: 1.3211x; 1.1019x over previous
#include <cuda_runtime.h>
#include <cuda_bf16.h>
#include <math.h>
#include <stdint.h>

// Problem constants
#define NN 50000
#define EE 400000
#define EP 450000      // E + N self loops
#define FF 128
#define H1 8
#define CC 64
#define HC 512         // H1*CC
#define BB 64
#define KK 10

// ---------------- scratch (device globals; no allocation allowed) ----------------
__device__ float g_h1[(size_t)NN * HC];      // x @ W1
__device__ float g_out1[(size_t)NN * HC];    // elu(gat1)
__device__ float g_h2[(size_t)NN * CC];      // out1 @ W2
__device__ float g_out2[(size_t)NN * CC];    // elu(gat2)
__device__ float g_as1[NN * H1];
__device__ float g_ad1[NN * H1];
__device__ float g_as2[NN];
__device__ float g_ad2[NN];
__device__ int   g_rowptr[NN + 1];
__device__ int   g_cursor[NN];
__device__ int   g_srcsorted[EP];
__device__ float g_pooled[BB * CC];
__device__ float g_W1T[HC * FF];             // W1^T : [512,128] (K-major B operand)
__device__ float g_W2T[CC * HC];             // W2^T : [64,512]

// ================= mma.sync helpers (sm_80+ PTX; valid on plain sm_103) =========
__device__ __forceinline__ void ldm_x4(uint32_t* r, uint32_t addr) {
    asm volatile("ldmatrix.sync.aligned.m8n8.x4.shared.b16 {%0,%1,%2,%3}, [%4];"
        : "=r"(r[0]), "=r"(r[1]), "=r"(r[2]), "=r"(r[3]) : "r"(addr));
}
__device__ __forceinline__ void ldm_x2(uint32_t* r, uint32_t addr) {
    asm volatile("ldmatrix.sync.aligned.m8n8.x2.shared.b16 {%0,%1}, [%2];"
        : "=r"(r[0]), "=r"(r[1]) : "r"(addr));
}
__device__ __forceinline__ void mma_bf16(float* c, const uint32_t* a, const uint32_t* b) {
    asm volatile("mma.sync.aligned.m16n8k16.row.col.f32.bf16.bf16.f32 "
        "{%0,%1,%2,%3}, {%4,%5,%6,%7}, {%8,%9}, {%0,%1,%2,%3};"
        : "+f"(c[0]), "+f"(c[1]), "+f"(c[2]), "+f"(c[3])
        : "r"(a[0]), "r"(a[1]), "r"(a[2]), "r"(a[3]), "r"(b[0]), "r"(b[1]));
}

// split a float into bf16 hi + bf16 lo (residual)
__device__ __forceinline__ void bsplit(float x, uint32_t& h, uint32_t& l) {
    __nv_bfloat16 hb = __float2bfloat16(x);
    float r = x - __bfloat162float(hb);
    h = (uint32_t)__bfloat16_as_ushort(hb);
    l = (uint32_t)__bfloat16_as_ushort(__float2bfloat16(r));
}
__device__ __forceinline__ void bsplit4(float4 v, uint2& hi, uint2& lo) {
    uint32_t h0, l0, h1, l1, h2, l2, h3, l3;
    bsplit(v.x, h0, l0); bsplit(v.y, h1, l1);
    bsplit(v.z, h2, l2); bsplit(v.w, h3, l3);
    hi.x = h0 | (h1 << 16); hi.y = h2 | (h3 << 16);
    lo.x = l0 | (l1 << 16); lo.y = l2 | (l3 << 16);
}

// ================= bf16x3 tensor-core GEMM + fused attention dots ==============
// C[M,NTOT] = A[M,KTOT] @ BT[NTOT,KTOT]^T   (BT is K-major: BT[n][k])
// BM=128, BK=32 floats; 256 threads (8 warps, 2x4 warp grid; warp tile 64 x BN/4).
// 3 passes per tile: Ahi*Bhi + Alo*Bhi + Ahi*Blo (bf16x3 precision trick).
// Fused epilogue: as_out[row*hstride+h] += dot(C_row[head h cols], attS),
// same for attD -> ad_out. Head span (64 cols) always contains a warp's n-span.
template <int KTOT, int BN>
__global__ void __launch_bounds__(256, 2) gemm_bf16x3_kernel(
    const float* __restrict__ A, const float* __restrict__ BT,
    float* __restrict__ C, int M, int NTOT,
    const float* __restrict__ attS, const float* __restrict__ attD,
    float* __restrict__ as_out, float* __restrict__ ad_out, int hstride) {
    constexpr int BM = 128, BK = 32;
    constexpr int NPANEL = KTOT / BK;
    constexpr int LDB_BYTES = 80;     // 32 bf16 padded to 40 (80 bytes)
    constexpr int WN = BN / 4;        // warp n-tile (32 or 16)
    constexpr int NT = WN / 8;        // n mma tiles per warp (4 or 2)
    constexpr int AV = 4;             // A float4 per thread (128*8/256)
    constexpr int BV = (BN * 8) / 256;

    __shared__ __align__(16) char sAhi[BM * LDB_BYTES];
    __shared__ __align__(16) char sAlo[BM * LDB_BYTES];
    __shared__ __align__(16) char sBhi[BN * LDB_BYTES];
    __shared__ __align__(16) char sBlo[BN * LDB_BYTES];

    const int tid = threadIdx.x, wid = tid >> 5, lane = tid & 31;
    const int wm = wid & 1, wn = wid >> 1;   // 2 x 4 warp grid
    const int m0 = blockIdx.y * BM, n0 = blockIdx.x * BN;

    const uint32_t aHiB = (uint32_t)__cvta_generic_to_shared(sAhi);
    const uint32_t aLoB = (uint32_t)__cvta_generic_to_shared(sAlo);
    const uint32_t bHiB = (uint32_t)__cvta_generic_to_shared(sBhi);
    const uint32_t bLoB = (uint32_t)__cvta_generic_to_shared(sBlo);

    float acc[4][NT][4];
#pragma unroll
    for (int i = 0; i < 4; i++)
#pragma unroll
        for (int j = 0; j < NT; j++)
#pragma unroll
            for (int q = 0; q < 4; q++) acc[i][j][q] = 0.f;

    // ldmatrix per-lane address offsets
    const int a_row = lane & 15;
    const int a_col = (lane >> 4) << 3;
    const int b_row = lane & 7;
    const int b_col = ((lane >> 3) & 1) << 3;

    const int a_frow = tid >> 3;          // A/B staging row for this thread
    const int a_fc4  = tid & 7;

    auto loadA = [&](int k0, float4* av) {
#pragma unroll
        for (int i = 0; i < AV; i++) {
            int row = a_frow + i * 32;
            int gm = m0 + row;
            av[i] = (gm < M)
                ? __ldg(reinterpret_cast<const float4*>(A + (size_t)gm * KTOT + k0 + a_fc4 * 4))
                : make_float4(0.f, 0.f, 0.f, 0.f);
        }
    };

    float4 av[AV];
    loadA(0, av);

    for (int p = 0; p < NPANEL; ++p) {
        int k0 = p * BK;
        // B loads for current panel (small, L2-hot)
        float4 bv[BV];
#pragma unroll
        for (int i = 0; i < BV; i++) {
            int row = a_frow + i * 32;
            bv[i] = __ldg(reinterpret_cast<const float4*>(BT + (size_t)(n0 + row) * KTOT + k0 + a_fc4 * 4));
        }
        __syncthreads();   // previous compute done with smem
        // ---- split to bf16 hi/lo and store to smem ----
#pragma unroll
        for (int i = 0; i < AV; i++) {
            int row = a_frow + i * 32;
            uint2 hi, lo;
            bsplit4(av[i], hi, lo);
            int off = row * LDB_BYTES + a_fc4 * 8;
            *reinterpret_cast<uint2*>(sAhi + off) = hi;
            *reinterpret_cast<uint2*>(sAlo + off) = lo;
        }
#pragma unroll
        for (int i = 0; i < BV; i++) {
            int row = a_frow + i * 32;
            uint2 hi, lo;
            bsplit4(bv[i], hi, lo);
            int off = row * LDB_BYTES + a_fc4 * 8;
            *reinterpret_cast<uint2*>(sBhi + off) = hi;
            *reinterpret_cast<uint2*>(sBlo + off) = lo;
        }
        __syncthreads();
        // prefetch next A panel (hidden under compute below)
        if (p + 1 < NPANEL) loadA(k0 + BK, av);
        // ---- compute: 2 k-steps of 16, 3 passes each ----
#pragma unroll
        for (int ks = 0; ks < 2; ks++) {
            int kk = ks * 16;
            uint32_t ah[4][4], al[4][4], bh[NT][2], bl[NT][2];
#pragma unroll
            for (int mt = 0; mt < 4; mt++) {
                uint32_t off = (uint32_t)((wm * 64 + mt * 16 + a_row) * LDB_BYTES + (kk + a_col) * 2);
                ldm_x4(ah[mt], aHiB + off);
                ldm_x4(al[mt], aLoB + off);
            }
#pragma unroll
            for (int nt = 0; nt < NT; nt++) {
                uint32_t off = (uint32_t)((wn * WN + nt * 8 + b_row) * LDB_BYTES + (kk + b_col) * 2);
                ldm_x2(bh[nt], bHiB + off);
                ldm_x2(bl[nt], bLoB + off);
            }
#pragma unroll
            for (int mt = 0; mt < 4; mt++)
#pragma unroll
                for (int nt = 0; nt < NT; nt++) mma_bf16(acc[mt][nt], ah[mt], bh[nt]);
#pragma unroll
            for (int mt = 0; mt < 4; mt++)
#pragma unroll
                for (int nt = 0; nt < NT; nt++) mma_bf16(acc[mt][nt], al[mt], bh[nt]);
#pragma unroll
            for (int mt = 0; mt < 4; mt++)
#pragma unroll
                for (int nt = 0; nt < NT; nt++) mma_bf16(acc[mt][nt], ah[mt], bl[nt]);
        }
    }

    // ---- epilogue: store C + fused attention dot products ----
    const int h = (n0 + wn * WN) >> 6;   // head this warp's n-span belongs to
#pragma unroll
    for (int mt = 0; mt < 4; mt++) {
        int r0 = m0 + wm * 64 + mt * 16 + (lane >> 2);
        int r1 = r0 + 8;
        float pas0 = 0.f, pad0 = 0.f, pas1 = 0.f, pad1 = 0.f;
#pragma unroll
        for (int nt = 0; nt < NT; nt++) {
            int col = n0 + wn * WN + nt * 8 + (lane & 3) * 2;
            if (r0 < M)
                *reinterpret_cast<float2*>(C + (size_t)r0 * NTOT + col) =
                    make_float2(acc[mt][nt][0], acc[mt][nt][1]);
            if (r1 < M)
                *reinterpret_cast<float2*>(C + (size_t)r1 * NTOT + col) =
                    make_float2(acc[mt][nt][2], acc[mt][nt][3]);
            float s0 = __ldg(attS + col), s1 = __ldg(attS + col + 1);
            float d0 = __ldg(attD + col), d1 = __ldg(attD + col + 1);
            pas0 += acc[mt][nt][0] * s0 + acc[mt][nt][1] * s1;
            pad0 += acc[mt][nt][0] * d0 + acc[mt][nt][1] * d1;
            pas1 += acc[mt][nt][2] * s0 + acc[mt][nt][3] * s1;
            pad1 += acc[mt][nt][2] * d0 + acc[mt][nt][3] * d1;
        }
        // reduce over the 4 lanes covering this row's 8-col groups
#pragma unroll
        for (int o = 1; o <= 2; o <<= 1) {
            pas0 += __shfl_xor_sync(~0u, pas0, o);
            pad0 += __shfl_xor_sync(~0u, pad0, o);
            pas1 += __shfl_xor_sync(~0u, pas1, o);
            pad1 += __shfl_xor_sync(~0u, pad1, o);
        }
        if ((lane & 3) == 0) {
            if (r0 < M) {
                atomicAdd(as_out + (size_t)r0 * hstride + h, pas0);
                atomicAdd(ad_out + (size_t)r0 * hstride + h, pad0);
            }
            if (r1 < M) {
                atomicAdd(as_out + (size_t)r1 * hstride + h, pas1);
                atomicAdd(ad_out + (size_t)r1 * hstride + h, pad1);
            }
        }
    }
}

// ---------------- weight transpose: dst[c*R + r] = src[r*C + c] ----------------
__global__ void transpose_kernel(const float* __restrict__ src, float* __restrict__ dst,
                                 int R, int C) {
    int i = blockIdx.x * blockDim.x + threadIdx.x;
    if (i < R * C) {
        int r = i / C, c = i % C;
        dst[c * R + r] = src[i];
    }
}

// ---------------- zero scratch: cursor, attention dot accumulators, pooled ------
__global__ void zero_all_kernel() {
    int i = blockIdx.x * blockDim.x + threadIdx.x;
    if (i < NN) {
        g_cursor[i] = 0;
        g_as2[i] = 0.f;
        g_ad2[i] = 0.f;
        float4 z = make_float4(0.f, 0.f, 0.f, 0.f);
        float4* p1 = reinterpret_cast<float4*>(g_as1 + i * H1);
        p1[0] = z; p1[1] = z;
        float4* p2 = reinterpret_cast<float4*>(g_ad1 + i * H1);
        p2[0] = z; p2[1] = z;
    }
    if (i < BB * CC) g_pooled[i] = 0.f;
}

// ---------------- CSR build ----------------
__global__ void count_edges_kernel(const int* __restrict__ ei) {
    int i = blockIdx.x * blockDim.x + threadIdx.x;
    if (i >= EP) return;
    int d = (i < EE) ? ei[EE + i] : (i - EE);
    atomicAdd(&g_cursor[d], 1);
}

__global__ void scan_kernel() {
    __shared__ int part[1024];
    int t = threadIdx.x;
    const int CH = (NN + 1023) / 1024;  // 49
    int base = t * CH;
    int s = 0;
    for (int i = 0; i < CH; i++) {
        int idx = base + i;
        if (idx < NN) s += g_cursor[idx];
    }
    part[t] = s;
    __syncthreads();
    for (int o = 1; o < 1024; o <<= 1) {
        int v = (t >= o) ? part[t - o] : 0;
        __syncthreads();
        part[t] += v;
        __syncthreads();
    }
    int run = part[t] - s;  // exclusive
    for (int i = 0; i < CH; i++) {
        int idx = base + i;
        if (idx < NN) {
            int c = g_cursor[idx];
            g_rowptr[idx] = run;
            g_cursor[idx] = run;
            run += c;
        }
    }
    if (t == 1023) g_rowptr[NN] = part[1023];
}

__global__ void scatter_edges_kernel(const int* __restrict__ ei) {
    int i = blockIdx.x * blockDim.x + threadIdx.x;
    if (i >= EP) return;
    int s, d;
    if (i < EE) { s = ei[i]; d = ei[EE + i]; }
    else        { s = i - EE; d = s; }
    int pos = atomicAdd(&g_cursor[d], 1);
    g_srcsorted[pos] = s;
}

// ---------------- layer-1 aggregation (softmax + weighted sum + elu) ----------------
// block = node, warp = head. Raw logits cached in smem: as1 gathered ONCE.
__global__ void agg1_kernel(const float* __restrict__ bias) {
    __shared__ float ebuf[H1][64];
    int n = blockIdx.x;
    int h = threadIdx.x >> 5;
    int lane = threadIdx.x & 31;
    int base = g_rowptr[n];
    int deg = g_rowptr[n + 1] - base;
    float adn = g_ad1[n * H1 + h];

    float m = -INFINITY;
    for (int j = lane; j < deg; j += 32) {
        int s = g_srcsorted[base + j];
        float e = g_as1[s * H1 + h] + adn;
        e = e > 0.f ? e : 0.2f * e;
        if (j < 64) ebuf[h][j] = e;
        m = fmaxf(m, e);
    }
#pragma unroll
    for (int o = 16; o; o >>= 1) m = fmaxf(m, __shfl_xor_sync(~0u, m, o));

    float sum = 0.f;
    for (int j = lane; j < deg; j += 32) {
        float e;
        if (j < 64) e = ebuf[h][j];
        else {
            int s = g_srcsorted[base + j];
            e = g_as1[s * H1 + h] + adn;
            e = e > 0.f ? e : 0.2f * e;
        }
        sum += __expf(e - m);
    }
#pragma unroll
    for (int o = 16; o; o >>= 1) sum += __shfl_xor_sync(~0u, sum, o);
    float inv = 1.f / (sum + 1e-16f);
    __syncwarp();

    float acc0 = 0.f, acc1 = 0.f;
    for (int j = 0; j < deg; j++) {
        int s = g_srcsorted[base + j];
        float e;
        if (j < 64) e = ebuf[h][j];
        else {
            e = g_as1[s * H1 + h] + adn;
            e = e > 0.f ? e : 0.2f * e;
        }
        float a = __expf(e - m) * inv;
        const float* hp = g_h1 + (size_t)s * HC + h * CC;
        acc0 += hp[lane] * a;
        acc1 += hp[lane + 32] * a;
    }
    float v0 = acc0 + bias[h * CC + lane];
    float v1 = acc1 + bias[h * CC + lane + 32];
    v0 = v0 > 0.f ? v0 : expm1f(v0);
    v1 = v1 > 0.f ? v1 : expm1f(v1);
    g_out1[(size_t)n * HC + h * CC + lane] = v0;
    g_out1[(size_t)n * HC + h * CC + lane + 32] = v1;
}

// ---------------- layer-2 aggregation (1 head, C=64) ----------------
__global__ void agg2_kernel(const float* __restrict__ bias) {
    __shared__ float ebuf[8][64];
    int w = threadIdx.x >> 5;
    int lane = threadIdx.x & 31;
    int n = blockIdx.x * 8 + w;
    if (n >= NN) return;
    int base = g_rowptr[n];
    int deg = g_rowptr[n + 1] - base;
    float adn = g_ad2[n];

    float m = -INFINITY;
    for (int j = lane; j < deg; j += 32) {
        int s = g_srcsorted[base + j];
        float e = g_as2[s] + adn;
        e = e > 0.f ? e : 0.2f * e;
        if (j < 64) ebuf[w][j] = e;
        m = fmaxf(m, e);
    }
#pragma unroll
    for (int o = 16; o; o >>= 1) m = fmaxf(m, __shfl_xor_sync(~0u, m, o));

    float sum = 0.f;
    for (int j = lane; j < deg; j += 32) {
        float e;
        if (j < 64) e = ebuf[w][j];
        else {
            int s = g_srcsorted[base + j];
            e = g_as2[s] + adn;
            e = e > 0.f ? e : 0.2f * e;
        }
        sum += __expf(e - m);
    }
#pragma unroll
    for (int o = 16; o; o >>= 1) sum += __shfl_xor_sync(~0u, sum, o);
    float inv = 1.f / (sum + 1e-16f);
    __syncwarp();

    float acc0 = 0.f, acc1 = 0.f;
    for (int j = 0; j < deg; j++) {
        int s = g_srcsorted[base + j];
        float e;
        if (j < 64) e = ebuf[w][j];
        else {
            e = g_as2[s] + adn;
            e = e > 0.f ? e : 0.2f * e;
        }
        float a = __expf(e - m) * inv;
        const float* hp = g_h2 + (size_t)s * CC;
        acc0 += hp[lane] * a;
        acc1 += hp[lane + 32] * a;
    }
    float v0 = acc0 + bias[lane];
    float v1 = acc1 + bias[lane + 32];
    v0 = v0 > 0.f ? v0 : expm1f(v0);
    v1 = v1 > 0.f ? v1 : expm1f(v1);
    g_out2[(size_t)n * CC + lane] = v0;
    g_out2[(size_t)n * CC + lane + 32] = v1;
}

// ---------------- pooling (batch sorted -> flush-on-change) ----------------
__global__ void pool_kernel(const int* __restrict__ batch) {
    int c = threadIdx.x & 63;
    int nl = threadIdx.x >> 6;      // 0..3
    int n0 = blockIdx.x * 256;
    int nend = min(n0 + 256, NN);
    float acc = 0.f;
    int cur = -1;
    for (int n = n0 + nl; n < nend; n += 4) {
        int bt = batch[n];
        if (bt != cur) {
            if (cur >= 0) atomicAdd(&g_pooled[cur * CC + c], acc);
            cur = bt;
            acc = 0.f;
        }
        acc += g_out2[(size_t)n * CC + c];
    }
    if (cur >= 0) atomicAdd(&g_pooled[cur * CC + c], acc);
}

// ---------------- MLP head + log_softmax ----------------
__global__ void head_kernel(const float* __restrict__ lin1_w, const float* __restrict__ lin1_b,
                            const float* __restrict__ lin2_w, const float* __restrict__ lin2_b,
                            float* __restrict__ out) {
    __shared__ float p[CC], z[CC], lg[KK];
    __shared__ float lse;
    int t = threadIdx.x;
    int g = blockIdx.x;
    p[t] = g_pooled[g * CC + t];
    __syncthreads();
    float zz = lin1_b[t];
    for (int i = 0; i < CC; i++) zz += p[i] * lin1_w[i * CC + t];
    zz = zz > 0.f ? zz : expm1f(zz);
    z[t] = zz;
    __syncthreads();
    if (t < KK) {
        float l = lin2_b[t];
        for (int i = 0; i < CC; i++) l += z[i] * lin2_w[i * KK + t];
        lg[t] = l;
    }
    __syncthreads();
    if (t == 0) {
        float m = -INFINITY;
        for (int i = 0; i < KK; i++) m = fmaxf(m, lg[i]);
        float s = 0.f;
        for (int i = 0; i < KK; i++) s += expf(lg[i] - m);
        lse = m + logf(s);
    }
    __syncthreads();
    if (t < KK) out[g * KK + t] = lg[t] - lse;
}

// ---------------- launch ----------------
extern "C" void kernel_launch(void* const* d_in, const int* in_sizes, int n_in,
                              void* d_out, int out_size) {
    const float* x        = (const float*)d_in[0];
    const int*   ei       = (const int*)d_in[1];
    const int*   batch    = (const int*)d_in[2];
    const float* W1       = (const float*)d_in[3];
    const float* att_src1 = (const float*)d_in[4];
    const float* att_dst1 = (const float*)d_in[5];
    const float* b1       = (const float*)d_in[6];
    const float* W2       = (const float*)d_in[7];
    const float* att_src2 = (const float*)d_in[8];
    const float* att_dst2 = (const float*)d_in[9];
    const float* b2       = (const float*)d_in[10];
    const float* lin1_w   = (const float*)d_in[11];
    const float* lin1_b   = (const float*)d_in[12];
    const float* lin2_w   = (const float*)d_in[13];
    const float* lin2_b   = (const float*)d_in[14];
    float* out = (float*)d_out;

    float *w1t, *w2t, *h1, *o1, *h2, *as1, *ad1, *as2, *ad2;
    cudaGetSymbolAddress((void**)&w1t, g_W1T);
    cudaGetSymbolAddress((void**)&w2t, g_W2T);
    cudaGetSymbolAddress((void**)&h1, g_h1);
    cudaGetSymbolAddress((void**)&o1, g_out1);
    cudaGetSymbolAddress((void**)&h2, g_h2);
    cudaGetSymbolAddress((void**)&as1, g_as1);
    cudaGetSymbolAddress((void**)&ad1, g_ad1);
    cudaGetSymbolAddress((void**)&as2, g_as2);
    cudaGetSymbolAddress((void**)&ad2, g_ad2);

    // weight transposes (K-major B operands)
    transpose_kernel<<<(FF * HC + 255) / 256, 256>>>(W1, w1t, FF, HC);
    transpose_kernel<<<(HC * CC + 255) / 256, 256>>>(W2, w2t, HC, CC);

    // zero cursor + attention accumulators + pooled
    zero_all_kernel<<<(NN + 255) / 256, 256>>>();

    // CSR build
    count_edges_kernel<<<(EP + 255) / 256, 256>>>(ei);
    scan_kernel<<<1, 1024>>>();
    scatter_edges_kernel<<<(EP + 255) / 256, 256>>>(ei);

    // layer 1: h1 = x @ W1 (bf16x3 tensor cores) + fused att1 dots
    {
        dim3 grid(HC / 128, (NN + 127) / 128);
        gemm_bf16x3_kernel<FF, 128><<<grid, 256>>>(x, w1t, h1, NN, HC,
                                                   att_src1, att_dst1, as1, ad1, H1);
    }
    agg1_kernel<<<NN, 256>>>(b1);

    // layer 2: h2 = out1 @ W2 + fused att2 dots
    {
        dim3 grid(CC / 64, (NN + 127) / 128);
        gemm_bf16x3_kernel<HC, 64><<<grid, 256>>>(o1, w2t, h2, NN, CC,
                                                  att_src2, att_dst2, as2, ad2, 1);
    }
    agg2_kernel<<<(NN + 7) / 8, 256>>>(b2);

    // pool + head
    pool_kernel<<<(NN + 255) / 256, 256>>>(batch);
    head_kernel<<<BB, CC>>>(lin1_w, lin1_b, lin2_w, lin2_b, out);
}

// round 11
// speedup vs baseline: 1.3722x; 1.0387x over previous
#include <cuda_runtime.h>
#include <cuda_bf16.h>
#include <math.h>
#include <stdint.h>

// Problem constants
#define NN 50000
#define EE 400000
#define EP 450000      // E + N self loops
#define FF 128
#define H1 8
#define CC 64
#define HC 512         // H1*CC
#define BB 64
#define KK 10

// ---------------- scratch (device globals; no allocation allowed) ----------------
// g_h1 / g_h2 hold BF16 data (packed bf16x2), allocated as float for alignment.
__device__ float g_h1[(size_t)NN * HC / 2];  // bf16[NN*HC]
__device__ float g_out1[(size_t)NN * HC];    // elu(gat1), fp32 (gemm2 input)
__device__ float g_h2[(size_t)NN * CC / 2];  // bf16[NN*CC]
__device__ float g_out2[(size_t)NN * CC];    // elu(gat2)
__device__ float g_as1[NN * H1];
__device__ float g_ad1[NN * H1];
__device__ float g_as2[NN];
__device__ float g_ad2[NN];
__device__ int   g_rowptr[NN + 1];
__device__ int   g_cursor[NN];
__device__ int   g_srcsorted[EP];
__device__ float g_pooled[BB * CC];
__device__ float g_W1T[HC * FF];             // W1^T : [512,128] (K-major B operand)
__device__ float g_W2T[CC * HC];             // W2^T : [64,512]

// ================= mma.sync helpers (sm_80+ PTX; valid on plain sm_103) =========
__device__ __forceinline__ void ldm_x4(uint32_t* r, uint32_t addr) {
    asm volatile("ldmatrix.sync.aligned.m8n8.x4.shared.b16 {%0,%1,%2,%3}, [%4];"
        : "=r"(r[0]), "=r"(r[1]), "=r"(r[2]), "=r"(r[3]) : "r"(addr));
}
__device__ __forceinline__ void ldm_x2(uint32_t* r, uint32_t addr) {
    asm volatile("ldmatrix.sync.aligned.m8n8.x2.shared.b16 {%0,%1}, [%2];"
        : "=r"(r[0]), "=r"(r[1]) : "r"(addr));
}
__device__ __forceinline__ void mma_bf16(float* c, const uint32_t* a, const uint32_t* b) {
    asm volatile("mma.sync.aligned.m16n8k16.row.col.f32.bf16.bf16.f32 "
        "{%0,%1,%2,%3}, {%4,%5,%6,%7}, {%8,%9}, {%0,%1,%2,%3};"
        : "+f"(c[0]), "+f"(c[1]), "+f"(c[2]), "+f"(c[3])
        : "r"(a[0]), "r"(a[1]), "r"(a[2]), "r"(a[3]), "r"(b[0]), "r"(b[1]));
}

// split a float into bf16 hi + bf16 lo (residual)
__device__ __forceinline__ void bsplit(float x, uint32_t& h, uint32_t& l) {
    __nv_bfloat16 hb = __float2bfloat16(x);
    float r = x - __bfloat162float(hb);
    h = (uint32_t)__bfloat16_as_ushort(hb);
    l = (uint32_t)__bfloat16_as_ushort(__float2bfloat16(r));
}
__device__ __forceinline__ void bsplit4(float4 v, uint2& hi, uint2& lo) {
    uint32_t h0, l0, h1, l1, h2, l2, h3, l3;
    bsplit(v.x, h0, l0); bsplit(v.y, h1, l1);
    bsplit(v.z, h2, l2); bsplit(v.w, h3, l3);
    hi.x = h0 | (h1 << 16); hi.y = h2 | (h3 << 16);
    lo.x = l0 | (l1 << 16); lo.y = l2 | (l3 << 16);
}

// ================= bf16x3 tensor-core GEMM + fused attention dots ==============
// C[M,NTOT] = A[M,KTOT] @ BT[NTOT,KTOT]^T   (BT is K-major: BT[n][k])
// BM=128, BK=32 floats; 256 threads (8 warps, 2x4 warp grid; warp tile 64 x BN/4).
// 3 passes per tile: Ahi*Bhi + Alo*Bhi + Ahi*Blo (bf16x3 precision trick).
// C stored as packed bf16x2 (CBF16=true) or fp32.
// Fused epilogue: as_out[row*hstride+h] += dot(C_row[head h cols], attS) (fp32 accs).
template <int KTOT, int BN, bool CBF16>
__global__ void __launch_bounds__(256, 2) gemm_bf16x3_kernel(
    const float* __restrict__ A, const float* __restrict__ BT,
    float* __restrict__ C, int M, int NTOT,
    const float* __restrict__ attS, const float* __restrict__ attD,
    float* __restrict__ as_out, float* __restrict__ ad_out, int hstride) {
    constexpr int BM = 128, BK = 32;
    constexpr int NPANEL = KTOT / BK;
    constexpr int LDB_BYTES = 80;     // 32 bf16 padded to 40 (80 bytes)
    constexpr int WN = BN / 4;        // warp n-tile (32 or 16)
    constexpr int NT = WN / 8;        // n mma tiles per warp (4 or 2)
    constexpr int AV = 4;             // A float4 per thread (128*8/256)
    constexpr int BV = (BN * 8) / 256;

    __shared__ __align__(16) char sAhi[BM * LDB_BYTES];
    __shared__ __align__(16) char sAlo[BM * LDB_BYTES];
    __shared__ __align__(16) char sBhi[BN * LDB_BYTES];
    __shared__ __align__(16) char sBlo[BN * LDB_BYTES];

    const int tid = threadIdx.x, wid = tid >> 5, lane = tid & 31;
    const int wm = wid & 1, wn = wid >> 1;   // 2 x 4 warp grid
    const int m0 = blockIdx.y * BM, n0 = blockIdx.x * BN;

    const uint32_t aHiB = (uint32_t)__cvta_generic_to_shared(sAhi);
    const uint32_t aLoB = (uint32_t)__cvta_generic_to_shared(sAlo);
    const uint32_t bHiB = (uint32_t)__cvta_generic_to_shared(sBhi);
    const uint32_t bLoB = (uint32_t)__cvta_generic_to_shared(sBlo);

    float acc[4][NT][4];
#pragma unroll
    for (int i = 0; i < 4; i++)
#pragma unroll
        for (int j = 0; j < NT; j++)
#pragma unroll
            for (int q = 0; q < 4; q++) acc[i][j][q] = 0.f;

    // ldmatrix per-lane address offsets
    const int a_row = lane & 15;
    const int a_col = (lane >> 4) << 3;
    const int b_row = lane & 7;
    const int b_col = ((lane >> 3) & 1) << 3;

    const int a_frow = tid >> 3;          // A/B staging row for this thread
    const int a_fc4  = tid & 7;

    auto loadA = [&](int k0, float4* av) {
#pragma unroll
        for (int i = 0; i < AV; i++) {
            int row = a_frow + i * 32;
            int gm = m0 + row;
            av[i] = (gm < M)
                ? __ldg(reinterpret_cast<const float4*>(A + (size_t)gm * KTOT + k0 + a_fc4 * 4))
                : make_float4(0.f, 0.f, 0.f, 0.f);
        }
    };

    float4 av[AV];
    loadA(0, av);

    for (int p = 0; p < NPANEL; ++p) {
        int k0 = p * BK;
        float4 bv[BV];
#pragma unroll
        for (int i = 0; i < BV; i++) {
            int row = a_frow + i * 32;
            bv[i] = __ldg(reinterpret_cast<const float4*>(BT + (size_t)(n0 + row) * KTOT + k0 + a_fc4 * 4));
        }
        __syncthreads();   // previous compute done with smem
#pragma unroll
        for (int i = 0; i < AV; i++) {
            int row = a_frow + i * 32;
            uint2 hi, lo;
            bsplit4(av[i], hi, lo);
            int off = row * LDB_BYTES + a_fc4 * 8;
            *reinterpret_cast<uint2*>(sAhi + off) = hi;
            *reinterpret_cast<uint2*>(sAlo + off) = lo;
        }
#pragma unroll
        for (int i = 0; i < BV; i++) {
            int row = a_frow + i * 32;
            uint2 hi, lo;
            bsplit4(bv[i], hi, lo);
            int off = row * LDB_BYTES + a_fc4 * 8;
            *reinterpret_cast<uint2*>(sBhi + off) = hi;
            *reinterpret_cast<uint2*>(sBlo + off) = lo;
        }
        __syncthreads();
        if (p + 1 < NPANEL) loadA(k0 + BK, av);   // prefetch next A panel
#pragma unroll
        for (int ks = 0; ks < 2; ks++) {
            int kk = ks * 16;
            uint32_t ah[4][4], al[4][4], bh[NT][2], bl[NT][2];
#pragma unroll
            for (int mt = 0; mt < 4; mt++) {
                uint32_t off = (uint32_t)((wm * 64 + mt * 16 + a_row) * LDB_BYTES + (kk + a_col) * 2);
                ldm_x4(ah[mt], aHiB + off);
                ldm_x4(al[mt], aLoB + off);
            }
#pragma unroll
            for (int nt = 0; nt < NT; nt++) {
                uint32_t off = (uint32_t)((wn * WN + nt * 8 + b_row) * LDB_BYTES + (kk + b_col) * 2);
                ldm_x2(bh[nt], bHiB + off);
                ldm_x2(bl[nt], bLoB + off);
            }
#pragma unroll
            for (int mt = 0; mt < 4; mt++)
#pragma unroll
                for (int nt = 0; nt < NT; nt++) mma_bf16(acc[mt][nt], ah[mt], bh[nt]);
#pragma unroll
            for (int mt = 0; mt < 4; mt++)
#pragma unroll
                for (int nt = 0; nt < NT; nt++) mma_bf16(acc[mt][nt], al[mt], bh[nt]);
#pragma unroll
            for (int mt = 0; mt < 4; mt++)
#pragma unroll
                for (int nt = 0; nt < NT; nt++) mma_bf16(acc[mt][nt], ah[mt], bl[nt]);
        }
    }

    // ---- epilogue: store C (fp32 or packed bf16x2) + fused attention dots ----
    const int h = (n0 + wn * WN) >> 6;   // head this warp's n-span belongs to
#pragma unroll
    for (int mt = 0; mt < 4; mt++) {
        int r0 = m0 + wm * 64 + mt * 16 + (lane >> 2);
        int r1 = r0 + 8;
        float pas0 = 0.f, pad0 = 0.f, pas1 = 0.f, pad1 = 0.f;
#pragma unroll
        for (int nt = 0; nt < NT; nt++) {
            int col = n0 + wn * WN + nt * 8 + (lane & 3) * 2;
            if (CBF16) {
                __nv_bfloat16* Cb = reinterpret_cast<__nv_bfloat16*>(C);
                if (r0 < M)
                    *reinterpret_cast<__nv_bfloat162*>(Cb + (size_t)r0 * NTOT + col) =
                        __floats2bfloat162_rn(acc[mt][nt][0], acc[mt][nt][1]);
                if (r1 < M)
                    *reinterpret_cast<__nv_bfloat162*>(Cb + (size_t)r1 * NTOT + col) =
                        __floats2bfloat162_rn(acc[mt][nt][2], acc[mt][nt][3]);
            } else {
                if (r0 < M)
                    *reinterpret_cast<float2*>(C + (size_t)r0 * NTOT + col) =
                        make_float2(acc[mt][nt][0], acc[mt][nt][1]);
                if (r1 < M)
                    *reinterpret_cast<float2*>(C + (size_t)r1 * NTOT + col) =
                        make_float2(acc[mt][nt][2], acc[mt][nt][3]);
            }
            float s0 = __ldg(attS + col), s1 = __ldg(attS + col + 1);
            float d0 = __ldg(attD + col), d1 = __ldg(attD + col + 1);
            pas0 += acc[mt][nt][0] * s0 + acc[mt][nt][1] * s1;
            pad0 += acc[mt][nt][0] * d0 + acc[mt][nt][1] * d1;
            pas1 += acc[mt][nt][2] * s0 + acc[mt][nt][3] * s1;
            pad1 += acc[mt][nt][2] * d0 + acc[mt][nt][3] * d1;
        }
#pragma unroll
        for (int o = 1; o <= 2; o <<= 1) {
            pas0 += __shfl_xor_sync(~0u, pas0, o);
            pad0 += __shfl_xor_sync(~0u, pad0, o);
            pas1 += __shfl_xor_sync(~0u, pas1, o);
            pad1 += __shfl_xor_sync(~0u, pad1, o);
        }
        if ((lane & 3) == 0) {
            if (r0 < M) {
                atomicAdd(as_out + (size_t)r0 * hstride + h, pas0);
                atomicAdd(ad_out + (size_t)r0 * hstride + h, pad0);
            }
            if (r1 < M) {
                atomicAdd(as_out + (size_t)r1 * hstride + h, pas1);
                atomicAdd(ad_out + (size_t)r1 * hstride + h, pad1);
            }
        }
    }
}

// ---------------- weight transpose: dst[c*R + r] = src[r*C + c] ----------------
__global__ void transpose_kernel(const float* __restrict__ src, float* __restrict__ dst,
                                 int R, int C) {
    int i = blockIdx.x * blockDim.x + threadIdx.x;
    if (i < R * C) {
        int r = i / C, c = i % C;
        dst[c * R + r] = src[i];
    }
}

// ---------------- zero scratch ----------------
__global__ void zero_all_kernel() {
    int i = blockIdx.x * blockDim.x + threadIdx.x;
    if (i < NN) {
        g_cursor[i] = 0;
        g_as2[i] = 0.f;
        g_ad2[i] = 0.f;
        float4 z = make_float4(0.f, 0.f, 0.f, 0.f);
        float4* p1 = reinterpret_cast<float4*>(g_as1 + i * H1);
        p1[0] = z; p1[1] = z;
        float4* p2 = reinterpret_cast<float4*>(g_ad1 + i * H1);
        p2[0] = z; p2[1] = z;
    }
    if (i < BB * CC) g_pooled[i] = 0.f;
}

// ---------------- CSR build ----------------
__global__ void count_edges_kernel(const int* __restrict__ ei) {
    int i = blockIdx.x * blockDim.x + threadIdx.x;
    if (i >= EP) return;
    int d = (i < EE) ? ei[EE + i] : (i - EE);
    atomicAdd(&g_cursor[d], 1);
}

__global__ void scan_kernel() {
    __shared__ int part[1024];
    int t = threadIdx.x;
    const int CH = (NN + 1023) / 1024;  // 49
    int base = t * CH;
    int s = 0;
    for (int i = 0; i < CH; i++) {
        int idx = base + i;
        if (idx < NN) s += g_cursor[idx];
    }
    part[t] = s;
    __syncthreads();
    for (int o = 1; o < 1024; o <<= 1) {
        int v = (t >= o) ? part[t - o] : 0;
        __syncthreads();
        part[t] += v;
        __syncthreads();
    }
    int run = part[t] - s;  // exclusive
    for (int i = 0; i < CH; i++) {
        int idx = base + i;
        if (idx < NN) {
            int c = g_cursor[idx];
            g_rowptr[idx] = run;
            g_cursor[idx] = run;
            run += c;
        }
    }
    if (t == 1023) g_rowptr[NN] = part[1023];
}

__global__ void scatter_edges_kernel(const int* __restrict__ ei) {
    int i = blockIdx.x * blockDim.x + threadIdx.x;
    if (i >= EP) return;
    int s, d;
    if (i < EE) { s = ei[i]; d = ei[EE + i]; }
    else        { s = i - EE; d = s; }
    int pos = atomicAdd(&g_cursor[d], 1);
    g_srcsorted[pos] = s;
}

// ---------------- layer-1 aggregation (softmax + weighted sum + elu) ----------------
// block = node, warp = head. h1 gathered in BF16 (halved traffic); softmax fp32.
__global__ void agg1_kernel(const float* __restrict__ bias) {
    __shared__ float ebuf[H1][64];
    int n = blockIdx.x;
    int h = threadIdx.x >> 5;
    int lane = threadIdx.x & 31;
    int base = g_rowptr[n];
    int deg = g_rowptr[n + 1] - base;
    float adn = g_ad1[n * H1 + h];

    float m = -INFINITY;
    for (int j = lane; j < deg; j += 32) {
        int s = g_srcsorted[base + j];
        float e = g_as1[s * H1 + h] + adn;
        e = e > 0.f ? e : 0.2f * e;
        if (j < 64) ebuf[h][j] = e;
        m = fmaxf(m, e);
    }
#pragma unroll
    for (int o = 16; o; o >>= 1) m = fmaxf(m, __shfl_xor_sync(~0u, m, o));

    float sum = 0.f;
    for (int j = lane; j < deg; j += 32) {
        float e;
        if (j < 64) e = ebuf[h][j];
        else {
            int s = g_srcsorted[base + j];
            e = g_as1[s * H1 + h] + adn;
            e = e > 0.f ? e : 0.2f * e;
        }
        sum += __expf(e - m);
    }
#pragma unroll
    for (int o = 16; o; o >>= 1) sum += __shfl_xor_sync(~0u, sum, o);
    float inv = 1.f / (sum + 1e-16f);
    __syncwarp();

    const __nv_bfloat162* H = reinterpret_cast<const __nv_bfloat162*>(g_h1);
    float acc0 = 0.f, acc1 = 0.f;
    auto edgeE = [&](int j) -> float {
        if (j < 64) return ebuf[h][j];
        int s = g_srcsorted[base + j];
        float e = g_as1[s * H1 + h] + adn;
        return e > 0.f ? e : 0.2f * e;
    };
    int j = 0;
    for (; j + 2 <= deg; j += 2) {
        int s0 = g_srcsorted[base + j];
        int s1 = g_srcsorted[base + j + 1];
        float a0 = __expf(edgeE(j) - m) * inv;
        float a1 = __expf(edgeE(j + 1) - m) * inv;
        float2 v0 = __bfloat1622float2(H[(size_t)s0 * 256 + h * 32 + lane]);
        float2 v1 = __bfloat1622float2(H[(size_t)s1 * 256 + h * 32 + lane]);
        acc0 += v0.x * a0 + v1.x * a1;
        acc1 += v0.y * a0 + v1.y * a1;
    }
    if (j < deg) {
        int s0 = g_srcsorted[base + j];
        float a0 = __expf(edgeE(j) - m) * inv;
        float2 v0 = __bfloat1622float2(H[(size_t)s0 * 256 + h * 32 + lane]);
        acc0 += v0.x * a0;
        acc1 += v0.y * a0;
    }
    int c0 = h * CC + 2 * lane;
    float v0 = acc0 + bias[c0];
    float v1 = acc1 + bias[c0 + 1];
    v0 = v0 > 0.f ? v0 : expm1f(v0);
    v1 = v1 > 0.f ? v1 : expm1f(v1);
    *reinterpret_cast<float2*>(g_out1 + (size_t)n * HC + c0) = make_float2(v0, v1);
}

// ---------------- layer-2 aggregation (1 head, C=64), h2 gathered in BF16 -------
__global__ void agg2_kernel(const float* __restrict__ bias) {
    __shared__ float ebuf[8][64];
    int w = threadIdx.x >> 5;
    int lane = threadIdx.x & 31;
    int n = blockIdx.x * 8 + w;
    if (n >= NN) return;
    int base = g_rowptr[n];
    int deg = g_rowptr[n + 1] - base;
    float adn = g_ad2[n];

    float m = -INFINITY;
    for (int j = lane; j < deg; j += 32) {
        int s = g_srcsorted[base + j];
        float e = g_as2[s] + adn;
        e = e > 0.f ? e : 0.2f * e;
        if (j < 64) ebuf[w][j] = e;
        m = fmaxf(m, e);
    }
#pragma unroll
    for (int o = 16; o; o >>= 1) m = fmaxf(m, __shfl_xor_sync(~0u, m, o));

    float sum = 0.f;
    for (int j = lane; j < deg; j += 32) {
        float e;
        if (j < 64) e = ebuf[w][j];
        else {
            int s = g_srcsorted[base + j];
            e = g_as2[s] + adn;
            e = e > 0.f ? e : 0.2f * e;
        }
        sum += __expf(e - m);
    }
#pragma unroll
    for (int o = 16; o; o >>= 1) sum += __shfl_xor_sync(~0u, sum, o);
    float inv = 1.f / (sum + 1e-16f);
    __syncwarp();

    const __nv_bfloat162* H = reinterpret_cast<const __nv_bfloat162*>(g_h2);
    float acc0 = 0.f, acc1 = 0.f;
    auto edgeE = [&](int j) -> float {
        if (j < 64) return ebuf[w][j];
        int s = g_srcsorted[base + j];
        float e = g_as2[s] + adn;
        return e > 0.f ? e : 0.2f * e;
    };
    int j = 0;
    for (; j + 2 <= deg; j += 2) {
        int s0 = g_srcsorted[base + j];
        int s1 = g_srcsorted[base + j + 1];
        float a0 = __expf(edgeE(j) - m) * inv;
        float a1 = __expf(edgeE(j + 1) - m) * inv;
        float2 v0 = __bfloat1622float2(H[(size_t)s0 * 32 + lane]);
        float2 v1 = __bfloat1622float2(H[(size_t)s1 * 32 + lane]);
        acc0 += v0.x * a0 + v1.x * a1;
        acc1 += v0.y * a0 + v1.y * a1;
    }
    if (j < deg) {
        int s0 = g_srcsorted[base + j];
        float a0 = __expf(edgeE(j) - m) * inv;
        float2 v0 = __bfloat1622float2(H[(size_t)s0 * 32 + lane]);
        acc0 += v0.x * a0;
        acc1 += v0.y * a0;
    }
    int c0 = 2 * lane;
    float v0 = acc0 + bias[c0];
    float v1 = acc1 + bias[c0 + 1];
    v0 = v0 > 0.f ? v0 : expm1f(v0);
    v1 = v1 > 0.f ? v1 : expm1f(v1);
    *reinterpret_cast<float2*>(g_out2 + (size_t)n * CC + c0) = make_float2(v0, v1);
}

// ---------------- pooling (batch sorted -> flush-on-change) ----------------
__global__ void pool_kernel(const int* __restrict__ batch) {
    int c = threadIdx.x & 63;
    int nl = threadIdx.x >> 6;      // 0..3
    int n0 = blockIdx.x * 256;
    int nend = min(n0 + 256, NN);
    float acc = 0.f;
    int cur = -1;
    for (int n = n0 + nl; n < nend; n += 4) {
        int bt = batch[n];
        if (bt != cur) {
            if (cur >= 0) atomicAdd(&g_pooled[cur * CC + c], acc);
            cur = bt;
            acc = 0.f;
        }
        acc += g_out2[(size_t)n * CC + c];
    }
    if (cur >= 0) atomicAdd(&g_pooled[cur * CC + c], acc);
}

// ---------------- MLP head + log_softmax ----------------
__global__ void head_kernel(const float* __restrict__ lin1_w, const float* __restrict__ lin1_b,
                            const float* __restrict__ lin2_w, const float* __restrict__ lin2_b,
                            float* __restrict__ out) {
    __shared__ float p[CC], z[CC], lg[KK];
    __shared__ float lse;
    int t = threadIdx.x;
    int g = blockIdx.x;
    p[t] = g_pooled[g * CC + t];
    __syncthreads();
    float zz = lin1_b[t];
    for (int i = 0; i < CC; i++) zz += p[i] * lin1_w[i * CC + t];
    zz = zz > 0.f ? zz : expm1f(zz);
    z[t] = zz;
    __syncthreads();
    if (t < KK) {
        float l = lin2_b[t];
        for (int i = 0; i < CC; i++) l += z[i] * lin2_w[i * KK + t];
        lg[t] = l;
    }
    __syncthreads();
    if (t == 0) {
        float m = -INFINITY;
        for (int i = 0; i < KK; i++) m = fmaxf(m, lg[i]);
        float s = 0.f;
        for (int i = 0; i < KK; i++) s += expf(lg[i] - m);
        lse = m + logf(s);
    }
    __syncthreads();
    if (t < KK) out[g * KK + t] = lg[t] - lse;
}

// ---------------- launch ----------------
extern "C" void kernel_launch(void* const* d_in, const int* in_sizes, int n_in,
                              void* d_out, int out_size) {
    const float* x        = (const float*)d_in[0];
    const int*   ei       = (const int*)d_in[1];
    const int*   batch    = (const int*)d_in[2];
    const float* W1       = (const float*)d_in[3];
    const float* att_src1 = (const float*)d_in[4];
    const float* att_dst1 = (const float*)d_in[5];
    const float* b1       = (const float*)d_in[6];
    const float* W2       = (const float*)d_in[7];
    const float* att_src2 = (const float*)d_in[8];
    const float* att_dst2 = (const float*)d_in[9];
    const float* b2       = (const float*)d_in[10];
    const float* lin1_w   = (const float*)d_in[11];
    const float* lin1_b   = (const float*)d_in[12];
    const float* lin2_w   = (const float*)d_in[13];
    const float* lin2_b   = (const float*)d_in[14];
    float* out = (float*)d_out;

    float *w1t, *w2t, *h1, *o1, *h2, *as1, *ad1, *as2, *ad2;
    cudaGetSymbolAddress((void**)&w1t, g_W1T);
    cudaGetSymbolAddress((void**)&w2t, g_W2T);
    cudaGetSymbolAddress((void**)&h1, g_h1);
    cudaGetSymbolAddress((void**)&o1, g_out1);
    cudaGetSymbolAddress((void**)&h2, g_h2);
    cudaGetSymbolAddress((void**)&as1, g_as1);
    cudaGetSymbolAddress((void**)&ad1, g_ad1);
    cudaGetSymbolAddress((void**)&as2, g_as2);
    cudaGetSymbolAddress((void**)&ad2, g_ad2);

    // weight transposes (K-major B operands)
    transpose_kernel<<<(FF * HC + 255) / 256, 256>>>(W1, w1t, FF, HC);
    transpose_kernel<<<(HC * CC + 255) / 256, 256>>>(W2, w2t, HC, CC);

    // zero cursor + attention accumulators + pooled
    zero_all_kernel<<<(NN + 255) / 256, 256>>>();

    // CSR build
    count_edges_kernel<<<(EP + 255) / 256, 256>>>(ei);
    scan_kernel<<<1, 1024>>>();
    scatter_edges_kernel<<<(EP + 255) / 256, 256>>>(ei);

    // layer 1: h1 = x @ W1 (bf16x3 tensor cores, bf16 output) + fused att1 dots
    {
        dim3 grid(HC / 128, (NN + 127) / 128);
        gemm_bf16x3_kernel<FF, 128, true><<<grid, 256>>>(x, w1t, h1, NN, HC,
                                                         att_src1, att_dst1, as1, ad1, H1);
    }
    agg1_kernel<<<NN, 256>>>(b1);

    // layer 2: h2 = out1 @ W2 (bf16 output) + fused att2 dots
    {
        dim3 grid(CC / 64, (NN + 127) / 128);
        gemm_bf16x3_kernel<HC, 64, true><<<grid, 256>>>(o1, w2t, h2, NN, CC,
                                                        att_src2, att_dst2, as2, ad2, 1);
    }
    agg2_kernel<<<(NN + 7) / 8, 256>>>(b2);

    // pool + head
    pool_kernel<<<(NN + 255) / 256, 256>>>(batch);
    head_kernel<<<BB, CC>>>(lin1_w, lin1_b, lin2_w, lin2_b, out);
}